// round 1
// baseline (speedup 1.0000x reference)
#include <cuda_runtime.h>
#include <math.h>

#define C_DIM 256
#define M_DIM 196
#define BATCH 256
#define TRIU_LEN 32896  // 256*257/2
#define MAT_ELEMS (C_DIM * C_DIM)

// Scratch (allocation-free: __device__ globals)
__device__ float g_A [BATCH * MAT_ELEMS];
__device__ float g_Y [BATCH * MAT_ELEMS];
__device__ float g_Z [BATCH * MAT_ELEMS];
__device__ float g_ZY[BATCH * MAT_ELEMS];
__device__ float g_T [BATCH * MAT_ELEMS];
__device__ float g_mu[BATCH * C_DIM];
__device__ float g_norm[BATCH];

// ---------------------------------------------------------------------------
// Stats: per-channel mean + normA = trace(cov) = sum_c (E[x^2] - mu^2)
// ---------------------------------------------------------------------------
__global__ void stats_kernel(const float* __restrict__ x) {
    int b = blockIdx.x;
    int c = threadIdx.x;
    const float* xp = x + ((size_t)b * C_DIM + c) * M_DIM;
    float s = 0.f, s2 = 0.f;
#pragma unroll 4
    for (int m = 0; m < M_DIM; m++) {
        float v = xp[m];
        s += v;
        s2 += v * v;
    }
    float mu = s * (1.0f / M_DIM);
    g_mu[b * C_DIM + c] = mu;
    float contrib = s2 * (1.0f / M_DIM) - mu * mu;

    __shared__ float red[C_DIM];
    red[c] = contrib;
    __syncthreads();
    for (int off = C_DIM / 2; off > 0; off >>= 1) {
        if (c < off) red[c] += red[c + off];
        __syncthreads();
    }
    if (c == 0) g_norm[b] = red[0];
}

// ---------------------------------------------------------------------------
// Covariance GEMM: Ahat = ((X X^T)/M - mu mu^T) / normA  (X = [256 x 196])
// Also emits ZY0 = 0.5*(3I - Ahat) into g_Z (== initial Zk).
// Grid (4,4,BATCH), block (16,16). 64x64 tile, 4x4 per thread.
// ---------------------------------------------------------------------------
__global__ void cov_kernel(const float* __restrict__ x) {
    __shared__ float As[16][68];
    __shared__ float Bs[16][68];

    int b   = blockIdx.z;
    int ti0 = blockIdx.y * 64;
    int tj0 = blockIdx.x * 64;
    int tx = threadIdx.x, ty = threadIdx.y;
    int tid = ty * 16 + tx;
    int lrow = tid >> 2;           // 0..63
    int lk   = (tid & 3) * 4;      // 0,4,8,12

    const float* xb = x + (size_t)b * C_DIM * M_DIM;
    float acc[4][4] = {};

    for (int k0 = 0; k0 < M_DIM; k0 += 16) {
#pragma unroll
        for (int q = 0; q < 4; q++) {
            int k = k0 + lk + q;
            float av = 0.f, bv = 0.f;
            if (k < M_DIM) {
                av = xb[(ti0 + lrow) * M_DIM + k];
                bv = xb[(tj0 + lrow) * M_DIM + k];
            }
            As[lk + q][lrow] = av;   // As[k][i]
            Bs[lk + q][lrow] = bv;   // Bs[k][j] = X[j][k]  (transposed)
        }
        __syncthreads();
#pragma unroll
        for (int k = 0; k < 16; k++) {
            float a[4], bb[4];
#pragma unroll
            for (int q = 0; q < 4; q++) { a[q] = As[k][ty * 4 + q]; bb[q] = Bs[k][tx * 4 + q]; }
#pragma unroll
            for (int i = 0; i < 4; i++)
#pragma unroll
                for (int j = 0; j < 4; j++)
                    acc[i][j] = fmaf(a[i], bb[j], acc[i][j]);
        }
        __syncthreads();
    }

    float rn = 1.0f / g_norm[b];
    const float* mub = g_mu + b * C_DIM;
#pragma unroll
    for (int i = 0; i < 4; i++) {
        int gi = ti0 + ty * 4 + i;
        float mi = mub[gi];
#pragma unroll
        for (int j = 0; j < 4; j++) {
            int gj = tj0 + tx * 4 + j;
            float val = (acc[i][j] * (1.0f / M_DIM) - mi * mub[gj]) * rn;
            size_t off = ((size_t)b * C_DIM + gi) * C_DIM + gj;
            g_A[off] = val;
            g_Z[off] = (gi == gj ? 1.5f : 0.0f) - 0.5f * val;
        }
    }
}

// ---------------------------------------------------------------------------
// Generic batched 256x256x256 GEMM: C = A @ B, with epilogue MODE:
//   0: plain store
//   1: store 0.5*(3I - acc)
//   2: scale by sqrt(normA), write upper triangle to d_out
// Grid (4,4,BATCH), block (16,16).
// ---------------------------------------------------------------------------
template <int MODE>
__global__ void gemm_kernel(const float* __restrict__ A,
                            const float* __restrict__ B,
                            float* __restrict__ Cout) {
    __shared__ float As[16][68];
    __shared__ float Bs[16][68];

    int b   = blockIdx.z;
    int ti0 = blockIdx.y * 64;
    int tj0 = blockIdx.x * 64;
    int tx = threadIdx.x, ty = threadIdx.y;
    int tid = ty * 16 + tx;

    // A-tile loaders: 64 rows x 16 k, float4 over k, scatter-transpose
    int lrow = tid >> 2;          // 0..63
    int lk   = (tid & 3) * 4;     // 0,4,8,12
    // B-tile loaders: 16 rows(k) x 64 cols, float4 over cols
    int brow = tid >> 4;          // 0..15
    int bcol = (tid & 15) * 4;    // 0..60

    const float* Ab = A + (size_t)b * MAT_ELEMS;
    const float* Bb = B + (size_t)b * MAT_ELEMS;

    float acc[4][4] = {};

    for (int k0 = 0; k0 < C_DIM; k0 += 16) {
        float4 av = *(const float4*)&Ab[(ti0 + lrow) * C_DIM + k0 + lk];
        As[lk + 0][lrow] = av.x;
        As[lk + 1][lrow] = av.y;
        As[lk + 2][lrow] = av.z;
        As[lk + 3][lrow] = av.w;
        float4 bv = *(const float4*)&Bb[(k0 + brow) * C_DIM + tj0 + bcol];
        *(float4*)&Bs[brow][bcol] = bv;
        __syncthreads();
#pragma unroll
        for (int k = 0; k < 16; k++) {
            float4 a4 = *(const float4*)&As[k][ty * 4];
            float4 b4 = *(const float4*)&Bs[k][tx * 4];
            float a[4] = {a4.x, a4.y, a4.z, a4.w};
            float bb[4] = {b4.x, b4.y, b4.z, b4.w};
#pragma unroll
            for (int i = 0; i < 4; i++)
#pragma unroll
                for (int j = 0; j < 4; j++)
                    acc[i][j] = fmaf(a[i], bb[j], acc[i][j]);
        }
        __syncthreads();
    }

    if (MODE == 2) {
        float sc = sqrtf(g_norm[b]);
        float* outb = Cout + (size_t)b * TRIU_LEN;
#pragma unroll
        for (int i = 0; i < 4; i++) {
            int gi = ti0 + ty * 4 + i;
            int rowbase = gi * C_DIM - (gi * (gi - 1)) / 2 - gi;  // + gj gives triu offset
#pragma unroll
            for (int j = 0; j < 4; j++) {
                int gj = tj0 + tx * 4 + j;
                if (gj >= gi) outb[rowbase + gj] = acc[i][j] * sc;
            }
        }
    } else {
        float* Cb = Cout + (size_t)b * MAT_ELEMS;
#pragma unroll
        for (int i = 0; i < 4; i++) {
            int gi = ti0 + ty * 4 + i;
#pragma unroll
            for (int j = 0; j < 4; j++) {
                int gj = tj0 + tx * 4 + j;
                float v;
                if (MODE == 1)
                    v = (gi == gj ? 1.5f : 0.0f) - 0.5f * acc[i][j];
                else
                    v = acc[i][j];
                Cb[gi * C_DIM + gj] = v;
            }
        }
    }
}

// ---------------------------------------------------------------------------
// Launch: Newton-Schulz (ITER_N = 3)
//   ZY0 = 0.5(3I - Ahat); Y1 = Ahat@ZY0; Z1 = ZY0
//   ZY1 = 0.5(3I - Z1@Y1); Y2 = Y1@ZY1; Z2 = ZY1@Z1
//   E   = 0.5(3I - Z2@Y2); out = triu( (Y2@E) * sqrt(normA) )
// ---------------------------------------------------------------------------
extern "C" void kernel_launch(void* const* d_in, const int* in_sizes, int n_in,
                              void* d_out, int out_size) {
    const float* x = (const float*)d_in[0];
    float* out = (float*)d_out;

    float *A, *Y, *Z, *ZY, *T;
    cudaGetSymbolAddress((void**)&A,  g_A);
    cudaGetSymbolAddress((void**)&Y,  g_Y);
    cudaGetSymbolAddress((void**)&Z,  g_Z);
    cudaGetSymbolAddress((void**)&ZY, g_ZY);
    cudaGetSymbolAddress((void**)&T,  g_T);

    dim3 grid(4, 4, BATCH), blk(16, 16);

    stats_kernel<<<BATCH, C_DIM>>>(x);
    cov_kernel<<<grid, blk>>>(x);              // g_A = Ahat, g_Z = ZY0 (= Z1)
    gemm_kernel<0><<<grid, blk>>>(A, Z, Y);    // Y1 = Ahat @ ZY0
    gemm_kernel<1><<<grid, blk>>>(Z, Y, ZY);   // ZY1 = 0.5(3I - Z1@Y1)
    gemm_kernel<0><<<grid, blk>>>(Y, ZY, A);   // Y2 = Y1 @ ZY1   (reuse g_A)
    gemm_kernel<0><<<grid, blk>>>(ZY, Z, T);   // Z2 = ZY1 @ Z1
    gemm_kernel<1><<<grid, blk>>>(T, A, ZY);   // E = 0.5(3I - Z2@Y2)
    gemm_kernel<2><<<grid, blk>>>(A, ZY, out); // out = triu((Y2@E)*sqrt(normA))
}

// round 2
// speedup vs baseline: 1.0765x; 1.0765x over previous
#include <cuda_runtime.h>
#include <math.h>

#define C_DIM 256
#define M_DIM 196
#define BATCH 256
#define TRIU_LEN 32896  // 256*257/2
#define MAT_ELEMS (C_DIM * C_DIM)

#define BK 16
#define SMPAD 132  // 128 + 4 pad, keeps 16B alignment

// Scratch (allocation-free: __device__ globals)
__device__ float g_A [BATCH * MAT_ELEMS];
__device__ float g_Y [BATCH * MAT_ELEMS];
__device__ float g_Z [BATCH * MAT_ELEMS];
__device__ float g_ZY[BATCH * MAT_ELEMS];
__device__ float g_T [BATCH * MAT_ELEMS];
__device__ float g_mu[BATCH * C_DIM];
__device__ float g_norm[BATCH];

// ---------------------------------------------------------------------------
// Stats: per-channel mean + normA = trace(cov) = sum_c (E[x^2] - mu^2)
// ---------------------------------------------------------------------------
__global__ void stats_kernel(const float* __restrict__ x) {
    int b = blockIdx.x;
    int c = threadIdx.x;
    const float* xp = x + ((size_t)b * C_DIM + c) * M_DIM;
    float s = 0.f, s2 = 0.f;
#pragma unroll 4
    for (int m = 0; m < M_DIM; m++) {
        float v = xp[m];
        s += v;
        s2 += v * v;
    }
    float mu = s * (1.0f / M_DIM);
    g_mu[b * C_DIM + c] = mu;
    float contrib = s2 * (1.0f / M_DIM) - mu * mu;

    __shared__ float red[C_DIM];
    red[c] = contrib;
    __syncthreads();
    for (int off = C_DIM / 2; off > 0; off >>= 1) {
        if (c < off) red[c] += red[c + off];
        __syncthreads();
    }
    if (c == 0) g_norm[b] = red[0];
}

// ---------------------------------------------------------------------------
// Tile-pair mapping for symmetric outputs: blockIdx.x in {0,1,2}
//   0 -> (0,0) diag, 1 -> (0,1) off-diag (mirrored), 2 -> (1,1) diag
// ---------------------------------------------------------------------------

// ---------------------------------------------------------------------------
// Covariance: Ahat = ((X X^T)/M - mu mu^T)/normA, ZY0 = 1.5I - 0.5*Ahat
// X = [256 x 196]. Symmetric: 3 tiles of 128x128 per batch, mirror off-diag.
// 256 threads, 8x8 microtile.
// ---------------------------------------------------------------------------
__global__ __launch_bounds__(256, 2) void cov_kernel(const float* __restrict__ x) {
    __shared__ float As[BK][SMPAD];
    __shared__ float Bs[BK][SMPAD];

    int b  = blockIdx.z;
    int bx = blockIdx.x;
    int ti0 = (bx == 2) ? 128 : 0;
    int tj0 = (bx >= 1) ? 128 : 0;

    int tid = threadIdx.x;
    int tx = tid & 15, ty = tid >> 4;
    int arow = tid >> 2;          // 0..63 (+64 second half)
    int acol = (tid & 3) * 4;     // 0,4,8,12

    const float* xb = x + (size_t)b * C_DIM * M_DIM;
    float acc[8][8] = {};

    for (int k0 = 0; k0 < 208; k0 += BK) {
        int col = k0 + acol;
        bool ok = (col < M_DIM);  // 196 % 4 == 0 and col % 4 == 0 -> all-or-nothing
#pragma unroll
        for (int h = 0; h < 2; h++) {
            int r = arow + h * 64;
            float4 va = make_float4(0.f, 0.f, 0.f, 0.f);
            float4 vb = make_float4(0.f, 0.f, 0.f, 0.f);
            if (ok) {
                va = *(const float4*)&xb[(ti0 + r) * M_DIM + col];
                vb = *(const float4*)&xb[(tj0 + r) * M_DIM + col];
            }
            As[acol + 0][r] = va.x; As[acol + 1][r] = va.y;
            As[acol + 2][r] = va.z; As[acol + 3][r] = va.w;
            Bs[acol + 0][r] = vb.x; Bs[acol + 1][r] = vb.y;
            Bs[acol + 2][r] = vb.z; Bs[acol + 3][r] = vb.w;
        }
        __syncthreads();
#pragma unroll
        for (int k = 0; k < BK; k++) {
            float a[8], bb[8];
            *(float4*)&a[0]  = *(const float4*)&As[k][ty * 8];
            *(float4*)&a[4]  = *(const float4*)&As[k][ty * 8 + 4];
            *(float4*)&bb[0] = *(const float4*)&Bs[k][tx * 8];
            *(float4*)&bb[4] = *(const float4*)&Bs[k][tx * 8 + 4];
#pragma unroll
            for (int i = 0; i < 8; i++)
#pragma unroll
                for (int j = 0; j < 8; j++)
                    acc[i][j] = fmaf(a[i], bb[j], acc[i][j]);
        }
        __syncthreads();
    }

    float rn = 1.0f / g_norm[b];
    const float* mub = g_mu + b * C_DIM;
    float* Ab = g_A + (size_t)b * MAT_ELEMS;
    float* Zb = g_Z + (size_t)b * MAT_ELEMS;
    bool mirror = (bx == 1);
#pragma unroll
    for (int i = 0; i < 8; i++) {
        int gi = ti0 + ty * 8 + i;
        float mi = mub[gi];
#pragma unroll
        for (int j = 0; j < 8; j++) {
            int gj = tj0 + tx * 8 + j;
            float val = (acc[i][j] * (1.0f / M_DIM) - mi * mub[gj]) * rn;
            float zv = (gi == gj ? 1.5f : 0.0f) - 0.5f * val;
            Ab[gi * C_DIM + gj] = val;
            Zb[gi * C_DIM + gj] = zv;
            if (mirror) {
                Ab[gj * C_DIM + gi] = val;
                Zb[gj * C_DIM + gi] = zv;
            }
        }
    }
}

// ---------------------------------------------------------------------------
// Symmetric batched 256x256x256 GEMM: C = A @ B (A,B symmetric & commuting,
// so C is symmetric -> compute upper block-triangle, mirror off-diag tile).
// MODE 0: plain; MODE 1: 1.5I - 0.5*acc; MODE 2: triu(acc * sqrt(normA)) -> out
// Grid (3,1,BATCH), 256 threads, 8x8 microtile, 128x128 tile.
// ---------------------------------------------------------------------------
template <int MODE>
__global__ __launch_bounds__(256, 2) void gemm_kernel(const float* __restrict__ A,
                                                      const float* __restrict__ B,
                                                      float* __restrict__ Cout) {
    __shared__ float As[BK][SMPAD];
    __shared__ float Bs[BK][SMPAD];

    int b  = blockIdx.z;
    int bx = blockIdx.x;
    int ti0 = (bx == 2) ? 128 : 0;
    int tj0 = (bx >= 1) ? 128 : 0;

    int tid = threadIdx.x;
    int tx = tid & 15, ty = tid >> 4;
    int arow = tid >> 2;          // 0..63
    int acol = (tid & 3) * 4;     // 0,4,8,12
    int brow = tid >> 4;          // 0..15
    int bcol = (tid & 15) * 8;    // 0..120

    const float* Ab = A + (size_t)b * MAT_ELEMS;
    const float* Bb = B + (size_t)b * MAT_ELEMS;

    float acc[8][8] = {};

    for (int k0 = 0; k0 < C_DIM; k0 += BK) {
        // A tile: 128 rows x 16 k, transposed into As[k][m]
#pragma unroll
        for (int h = 0; h < 2; h++) {
            int r = arow + h * 64;
            float4 v = *(const float4*)&Ab[(ti0 + r) * C_DIM + k0 + acol];
            As[acol + 0][r] = v.x; As[acol + 1][r] = v.y;
            As[acol + 2][r] = v.z; As[acol + 3][r] = v.w;
        }
        // B tile: 16 k-rows x 128 cols, direct
        *(float4*)&Bs[brow][bcol]     = *(const float4*)&Bb[(k0 + brow) * C_DIM + tj0 + bcol];
        *(float4*)&Bs[brow][bcol + 4] = *(const float4*)&Bb[(k0 + brow) * C_DIM + tj0 + bcol + 4];
        __syncthreads();
#pragma unroll
        for (int k = 0; k < BK; k++) {
            float a[8], bb[8];
            *(float4*)&a[0]  = *(const float4*)&As[k][ty * 8];
            *(float4*)&a[4]  = *(const float4*)&As[k][ty * 8 + 4];
            *(float4*)&bb[0] = *(const float4*)&Bs[k][tx * 8];
            *(float4*)&bb[4] = *(const float4*)&Bs[k][tx * 8 + 4];
#pragma unroll
            for (int i = 0; i < 8; i++)
#pragma unroll
                for (int j = 0; j < 8; j++)
                    acc[i][j] = fmaf(a[i], bb[j], acc[i][j]);
        }
        __syncthreads();
    }

    if (MODE == 2) {
        float sc = sqrtf(g_norm[b]);
        float* outb = Cout + (size_t)b * TRIU_LEN;
#pragma unroll
        for (int i = 0; i < 8; i++) {
            int gi = ti0 + ty * 8 + i;
            int rowbase = gi * C_DIM - (gi * (gi - 1)) / 2 - gi;  // + gj -> triu offset
#pragma unroll
            for (int j = 0; j < 8; j++) {
                int gj = tj0 + tx * 8 + j;
                if (gj >= gi) outb[rowbase + gj] = acc[i][j] * sc;
            }
        }
    } else {
        float* Cb = Cout + (size_t)b * MAT_ELEMS;
        bool mirror = (bx == 1);
#pragma unroll
        for (int i = 0; i < 8; i++) {
            int gi = ti0 + ty * 8 + i;
#pragma unroll
            for (int j = 0; j < 8; j++) {
                int gj = tj0 + tx * 8 + j;
                float v;
                if (MODE == 1)
                    v = (gi == gj ? 1.5f : 0.0f) - 0.5f * acc[i][j];
                else
                    v = acc[i][j];
                Cb[gi * C_DIM + gj] = v;
                if (mirror) Cb[gj * C_DIM + gi] = v;
            }
        }
    }
}

// ---------------------------------------------------------------------------
// Launch: Newton-Schulz (ITER_N = 3)
//   ZY0 = 0.5(3I - Ahat); Y1 = Ahat@ZY0; Z1 = ZY0
//   ZY1 = 0.5(3I - Z1@Y1); Y2 = Y1@ZY1; Z2 = ZY1@Z1
//   E   = 0.5(3I - Z2@Y2); out = triu( (Y2@E) * sqrt(normA) )
// ---------------------------------------------------------------------------
extern "C" void kernel_launch(void* const* d_in, const int* in_sizes, int n_in,
                              void* d_out, int out_size) {
    const float* x = (const float*)d_in[0];
    float* out = (float*)d_out;

    float *A, *Y, *Z, *ZY, *T;
    cudaGetSymbolAddress((void**)&A,  g_A);
    cudaGetSymbolAddress((void**)&Y,  g_Y);
    cudaGetSymbolAddress((void**)&Z,  g_Z);
    cudaGetSymbolAddress((void**)&ZY, g_ZY);
    cudaGetSymbolAddress((void**)&T,  g_T);

    dim3 grid(3, 1, BATCH);

    stats_kernel<<<BATCH, C_DIM>>>(x);
    cov_kernel<<<grid, 256>>>(x);               // g_A = Ahat, g_Z = ZY0 (= Z1)
    gemm_kernel<0><<<grid, 256>>>(A, Z, Y);     // Y1 = Ahat @ ZY0
    gemm_kernel<1><<<grid, 256>>>(Z, Y, ZY);    // ZY1 = 0.5(3I - Z1@Y1)
    gemm_kernel<0><<<grid, 256>>>(Y, ZY, A);    // Y2 = Y1 @ ZY1   (reuse g_A)
    gemm_kernel<0><<<grid, 256>>>(ZY, Z, T);    // Z2 = ZY1 @ Z1
    gemm_kernel<1><<<grid, 256>>>(T, A, ZY);    // E = 0.5(3I - Z2@Y2)
    gemm_kernel<2><<<grid, 256>>>(A, ZY, out);  // out = triu((Y2@E)*sqrt(normA))
}

// round 3
// speedup vs baseline: 1.1143x; 1.0351x over previous
#include <cuda_runtime.h>
#include <math.h>

#define C_DIM 256
#define M_DIM 196
#define BATCH 256
#define TRIU_LEN 32896  // 256*257/2
#define MAT_ELEMS (C_DIM * C_DIM)

#define BK 16
#define SMPAD 132  // 128 + 4 pad, keeps 16B alignment

typedef unsigned long long u64;

// packed f32x2 helpers (Blackwell fp32x2 pipe; ptxas never emits these itself)
__device__ __forceinline__ u64 pack2(float lo, float hi) {
    u64 r;
    asm("mov.b64 %0, {%1, %2};" : "=l"(r) : "f"(lo), "f"(hi));
    return r;
}
__device__ __forceinline__ void ffma2(u64& d, u64 a, u64 b) {
    asm("fma.rn.f32x2 %0, %1, %2, %0;" : "+l"(d) : "l"(a), "l"(b));
}
__device__ __forceinline__ float2 unpack2(u64 v) {
    float2 r;
    asm("mov.b64 {%0, %1}, %2;" : "=f"(r.x), "=f"(r.y) : "l"(v));
    return r;
}

// Scratch (allocation-free: __device__ globals)
__device__ float g_A [BATCH * MAT_ELEMS];
__device__ float g_Y [BATCH * MAT_ELEMS];
__device__ float g_Z [BATCH * MAT_ELEMS];
__device__ float g_ZY[BATCH * MAT_ELEMS];
__device__ float g_T [BATCH * MAT_ELEMS];
__device__ float g_mu[BATCH * C_DIM];
__device__ float g_norm[BATCH];

// ---------------------------------------------------------------------------
// Stats: per-channel mean + normA = trace(cov)
// ---------------------------------------------------------------------------
__global__ void stats_kernel(const float* __restrict__ x) {
    int b = blockIdx.x;
    int c = threadIdx.x;
    const float* xp = x + ((size_t)b * C_DIM + c) * M_DIM;
    float s = 0.f, s2 = 0.f;
#pragma unroll 4
    for (int m = 0; m < M_DIM; m++) {
        float v = xp[m];
        s += v;
        s2 += v * v;
    }
    float mu = s * (1.0f / M_DIM);
    g_mu[b * C_DIM + c] = mu;
    float contrib = s2 * (1.0f / M_DIM) - mu * mu;

    __shared__ float red[C_DIM];
    red[c] = contrib;
    __syncthreads();
    for (int off = C_DIM / 2; off > 0; off >>= 1) {
        if (c < off) red[c] += red[c + off];
        __syncthreads();
    }
    if (c == 0) g_norm[b] = red[0];
}

// ---------------------------------------------------------------------------
// Core packed-FFMA2 microtile step: acc[8][4(j-pairs)] += a[i] * b[j]
// ---------------------------------------------------------------------------
#define MICRO_K_STEP(As_, Bs_, k_)                                           \
    {                                                                        \
        float a[8], bf[8];                                                   \
        *(float4*)&a[0]  = *(const float4*)&As_[k_][ty * 8];                 \
        *(float4*)&a[4]  = *(const float4*)&As_[k_][ty * 8 + 4];             \
        *(float4*)&bf[0] = *(const float4*)&Bs_[k_][tx * 8];                 \
        *(float4*)&bf[4] = *(const float4*)&Bs_[k_][tx * 8 + 4];             \
        u64 bp[4];                                                           \
        _Pragma("unroll") for (int j = 0; j < 4; j++)                        \
            bp[j] = pack2(bf[2 * j], bf[2 * j + 1]);                         \
        _Pragma("unroll") for (int i = 0; i < 8; i++) {                      \
            u64 ap = pack2(a[i], a[i]);                                      \
            _Pragma("unroll") for (int j = 0; j < 4; j++)                    \
                ffma2(acc[i][j], ap, bp[j]);                                 \
        }                                                                    \
    }

// ---------------------------------------------------------------------------
// Covariance: Ahat = ((X X^T)/M - mu mu^T)/normA, ZY0 = 1.5I - 0.5*Ahat
// Symmetric: 3 tiles of 128x128 per batch (bx: 0=(0,0), 1=(0,1) mirrored, 2=(1,1))
// ---------------------------------------------------------------------------
__global__ __launch_bounds__(256, 2) void cov_kernel(const float* __restrict__ x) {
    __shared__ float As[BK][SMPAD];
    __shared__ float Bs[BK][SMPAD];

    int b  = blockIdx.z;
    int bx = blockIdx.x;
    int ti0 = (bx == 2) ? 128 : 0;
    int tj0 = (bx >= 1) ? 128 : 0;

    int tid = threadIdx.x;
    int tx = tid & 15, ty = tid >> 4;
    int arow = tid >> 2;
    int acol = (tid & 3) * 4;

    const float* xb = x + (size_t)b * C_DIM * M_DIM;
    u64 acc[8][4] = {};

    for (int k0 = 0; k0 < 208; k0 += BK) {
        int col = k0 + acol;
        bool ok = (col < M_DIM);
#pragma unroll
        for (int h = 0; h < 2; h++) {
            int r = arow + h * 64;
            float4 va = make_float4(0.f, 0.f, 0.f, 0.f);
            float4 vb = make_float4(0.f, 0.f, 0.f, 0.f);
            if (ok) {
                va = *(const float4*)&xb[(ti0 + r) * M_DIM + col];
                vb = *(const float4*)&xb[(tj0 + r) * M_DIM + col];
            }
            As[acol + 0][r] = va.x; As[acol + 1][r] = va.y;
            As[acol + 2][r] = va.z; As[acol + 3][r] = va.w;
            Bs[acol + 0][r] = vb.x; Bs[acol + 1][r] = vb.y;
            Bs[acol + 2][r] = vb.z; Bs[acol + 3][r] = vb.w;
        }
        __syncthreads();
#pragma unroll
        for (int k = 0; k < BK; k++) MICRO_K_STEP(As, Bs, k)
        __syncthreads();
    }

    float rn = 1.0f / g_norm[b];
    const float* mub = g_mu + b * C_DIM;
    float* Ab = g_A + (size_t)b * MAT_ELEMS;
    float* Zb = g_Z + (size_t)b * MAT_ELEMS;
    bool mirror = (bx == 1);
#pragma unroll
    for (int i = 0; i < 8; i++) {
        int gi = ti0 + ty * 8 + i;
        float mi = mub[gi];
#pragma unroll
        for (int j = 0; j < 4; j++) {
            float2 p = unpack2(acc[i][j]);
#pragma unroll
            for (int h = 0; h < 2; h++) {
                int gj = tj0 + tx * 8 + 2 * j + h;
                float raw = (h == 0) ? p.x : p.y;
                float val = (raw * (1.0f / M_DIM) - mi * mub[gj]) * rn;
                float zv = (gi == gj ? 1.5f : 0.0f) - 0.5f * val;
                Ab[gi * C_DIM + gj] = val;
                Zb[gi * C_DIM + gj] = zv;
                if (mirror) {
                    Ab[gj * C_DIM + gi] = val;
                    Zb[gj * C_DIM + gi] = zv;
                }
            }
        }
    }
}

// ---------------------------------------------------------------------------
// GEMM body (shared by all variants): computes 128x128 tile acc = A@B for
// tile (ti0,tj0) of batch b. Returns via acc[][].
// ---------------------------------------------------------------------------
template <int MODE>  // 0 plain, 1: 1.5I-0.5acc, 2: triu*sqrt(norm)
__device__ __forceinline__ void gemm_tile(const float* __restrict__ Ab,
                                          const float* __restrict__ Bb,
                                          float* __restrict__ Cout,
                                          int b, int ti0, int tj0, bool mirror) {
    __shared__ float As[BK][SMPAD];
    __shared__ float Bs[BK][SMPAD];

    int tid = threadIdx.x;
    int tx = tid & 15, ty = tid >> 4;
    int arow = tid >> 2;
    int acol = (tid & 3) * 4;
    int brow = tid >> 4;
    int bcol = (tid & 15) * 8;

    u64 acc[8][4] = {};

    for (int k0 = 0; k0 < C_DIM; k0 += BK) {
#pragma unroll
        for (int h = 0; h < 2; h++) {
            int r = arow + h * 64;
            float4 v = *(const float4*)&Ab[(ti0 + r) * C_DIM + k0 + acol];
            As[acol + 0][r] = v.x; As[acol + 1][r] = v.y;
            As[acol + 2][r] = v.z; As[acol + 3][r] = v.w;
        }
        *(float4*)&Bs[brow][bcol]     = *(const float4*)&Bb[(k0 + brow) * C_DIM + tj0 + bcol];
        *(float4*)&Bs[brow][bcol + 4] = *(const float4*)&Bb[(k0 + brow) * C_DIM + tj0 + bcol + 4];
        __syncthreads();
#pragma unroll
        for (int k = 0; k < BK; k++) MICRO_K_STEP(As, Bs, k)
        __syncthreads();
    }

    if (MODE == 2) {
        float sc = sqrtf(g_norm[b]);
        float* outb = Cout + (size_t)b * TRIU_LEN;
#pragma unroll
        for (int i = 0; i < 8; i++) {
            int gi = ti0 + ty * 8 + i;
            int rowbase = gi * C_DIM - (gi * (gi - 1)) / 2 - gi;
#pragma unroll
            for (int j = 0; j < 4; j++) {
                float2 p = unpack2(acc[i][j]);
#pragma unroll
                for (int h = 0; h < 2; h++) {
                    int gj = tj0 + tx * 8 + 2 * j + h;
                    float v = ((h == 0) ? p.x : p.y) * sc;
                    if (gj >= gi) outb[rowbase + gj] = v;
                }
            }
        }
    } else {
        float* Cb = Cout + (size_t)b * MAT_ELEMS;
#pragma unroll
        for (int i = 0; i < 8; i++) {
            int gi = ti0 + ty * 8 + i;
#pragma unroll
            for (int j = 0; j < 4; j++) {
                float2 p = unpack2(acc[i][j]);
#pragma unroll
                for (int h = 0; h < 2; h++) {
                    int gj = tj0 + tx * 8 + 2 * j + h;
                    float raw = (h == 0) ? p.x : p.y;
                    float v = (MODE == 1)
                                  ? ((gi == gj ? 1.5f : 0.0f) - 0.5f * raw)
                                  : raw;
                    Cb[gi * C_DIM + gj] = v;
                    if (mirror) Cb[gj * C_DIM + gi] = v;
                }
            }
        }
    }
}

template <int MODE>
__global__ __launch_bounds__(256, 2) void gemm_kernel(const float* __restrict__ A,
                                                      const float* __restrict__ B,
                                                      float* __restrict__ Cout) {
    int bx = blockIdx.x;
    int ti0 = (bx == 2) ? 128 : 0;
    int tj0 = (bx >= 1) ? 128 : 0;
    gemm_tile<MODE>(A + (size_t)blockIdx.z * MAT_ELEMS,
                    B + (size_t)blockIdx.z * MAT_ELEMS,
                    Cout, blockIdx.z, ti0, tj0, bx == 1);
}

// Fused: blockIdx.y==0 -> C1 = A1@B1;  blockIdx.y==1 -> C2 = A2@B2  (both MODE 0)
__global__ __launch_bounds__(256, 2) void gemm_dual_kernel(
    const float* __restrict__ A1, const float* __restrict__ B1, float* __restrict__ C1,
    const float* __restrict__ A2, const float* __restrict__ B2, float* __restrict__ C2) {
    int bx = blockIdx.x;
    int ti0 = (bx == 2) ? 128 : 0;
    int tj0 = (bx >= 1) ? 128 : 0;
    const float* A = (blockIdx.y == 0) ? A1 : A2;
    const float* B = (blockIdx.y == 0) ? B1 : B2;
    float* C = (blockIdx.y == 0) ? C1 : C2;
    gemm_tile<0>(A + (size_t)blockIdx.z * MAT_ELEMS,
                 B + (size_t)blockIdx.z * MAT_ELEMS,
                 C, blockIdx.z, ti0, tj0, bx == 1);
}

// ---------------------------------------------------------------------------
// Launch: Newton-Schulz (ITER_N = 3)
// ---------------------------------------------------------------------------
extern "C" void kernel_launch(void* const* d_in, const int* in_sizes, int n_in,
                              void* d_out, int out_size) {
    const float* x = (const float*)d_in[0];
    float* out = (float*)d_out;

    float *A, *Y, *Z, *ZY, *T;
    cudaGetSymbolAddress((void**)&A,  g_A);
    cudaGetSymbolAddress((void**)&Y,  g_Y);
    cudaGetSymbolAddress((void**)&Z,  g_Z);
    cudaGetSymbolAddress((void**)&ZY, g_ZY);
    cudaGetSymbolAddress((void**)&T,  g_T);

    dim3 grid(3, 1, BATCH);
    dim3 grid2(3, 2, BATCH);

    stats_kernel<<<BATCH, C_DIM>>>(x);
    cov_kernel<<<grid, 256>>>(x);                 // g_A = Ahat, g_Z = ZY0 (= Z1)
    gemm_kernel<0><<<grid, 256>>>(A, Z, Y);       // Y1 = Ahat @ ZY0
    gemm_kernel<1><<<grid, 256>>>(Z, Y, ZY);      // ZY1 = 0.5(3I - Z1@Y1)
    gemm_dual_kernel<<<grid2, 256>>>(Y, ZY, A,    // Y2 = Y1 @ ZY1
                                     ZY, Z, T);   // Z2 = ZY1 @ Z1
    gemm_kernel<1><<<grid, 256>>>(T, A, ZY);      // E = 0.5(3I - Z2@Y2)
    gemm_kernel<2><<<grid, 256>>>(A, ZY, out);    // out = triu((Y2@E)*sqrt(normA))
}

// round 5
// speedup vs baseline: 2.6685x; 2.3948x over previous
#include <cuda_runtime.h>
#include <cuda_fp16.h>
#include <math.h>
#include <stdint.h>

#define C_DIM 256
#define M_DIM 196
#define BATCH 256
#define TRIU_LEN 32896  // 256*257/2
#define MAT_ELEMS (C_DIM * C_DIM)

#define BK 16              // k per pipeline stage (halves)
#define ROWB 48            // bytes per smem row: 16 halves (32B) + 16B pad
#define TILEB (128 * ROWB) // 6144 B per tile

// ---------------------------------------------------------------------------
// Scratch (allocation-free: __device__ globals)
// ---------------------------------------------------------------------------
__device__ float g_A [BATCH * MAT_ELEMS];
__device__ float g_Y [BATCH * MAT_ELEMS];
__device__ float g_Z [BATCH * MAT_ELEMS];
__device__ float g_ZY[BATCH * MAT_ELEMS];
__device__ float g_T [BATCH * MAT_ELEMS];
__device__ float g_mu[BATCH * C_DIM];
__device__ float g_norm[BATCH];

// ---------------------------------------------------------------------------
// MMA helpers (plain sm_103-legal tensor ISA: ldmatrix + mma.sync)
// ---------------------------------------------------------------------------
__device__ __forceinline__ void ldmx4(uint32_t* r, uint32_t saddr) {
    asm volatile("ldmatrix.sync.aligned.m8n8.x4.shared.b16 {%0,%1,%2,%3}, [%4];"
                 : "=r"(r[0]), "=r"(r[1]), "=r"(r[2]), "=r"(r[3])
                 : "r"(saddr));
}

__device__ __forceinline__ void mma16816(float* c, const uint32_t* a,
                                         uint32_t b0, uint32_t b1) {
    asm volatile(
        "mma.sync.aligned.m16n8k16.row.col.f32.f16.f16.f32 "
        "{%0,%1,%2,%3}, {%4,%5,%6,%7}, {%8,%9}, {%0,%1,%2,%3};"
        : "+f"(c[0]), "+f"(c[1]), "+f"(c[2]), "+f"(c[3])
        : "r"(a[0]), "r"(a[1]), "r"(a[2]), "r"(a[3]), "r"(b0), "r"(b1));
}

__device__ __forceinline__ uint32_t packh(__half a, __half b) {
    return (uint32_t)__half_as_ushort(a) | ((uint32_t)__half_as_ushort(b) << 16);
}

// split fp32x4 -> fp16 hi/lo, store 8B each to smem
__device__ __forceinline__ void split_sts(char* hiP, char* loP, float4 v) {
    __half hx = __float2half_rn(v.x), hy = __float2half_rn(v.y);
    __half hz = __float2half_rn(v.z), hw = __float2half_rn(v.w);
    __half lx = __float2half_rn(v.x - __half2float(hx));
    __half ly = __float2half_rn(v.y - __half2float(hy));
    __half lz = __float2half_rn(v.z - __half2float(hz));
    __half lw = __float2half_rn(v.w - __half2float(hw));
    *(uint2*)hiP = make_uint2(packh(hx, hy), packh(hz, hw));
    *(uint2*)loP = make_uint2(packh(lx, ly), packh(lz, lw));
}

// ldmatrix fragment address: 16 rows starting at baserow; lanes 16-31 take k+8
__device__ __forceinline__ uint32_t frag_addr(uint32_t tilebase, int baserow, int lane) {
    return tilebase + (uint32_t)(baserow + (lane & 15)) * ROWB + ((lane >> 4) & 1) * 16;
}

// ---------------------------------------------------------------------------
// Stats: per-channel mean + normA = trace(cov)
// ---------------------------------------------------------------------------
__global__ void stats_kernel(const float* __restrict__ x) {
    int b = blockIdx.x;
    int c = threadIdx.x;
    const float* xp = x + ((size_t)b * C_DIM + c) * M_DIM;
    float s = 0.f, s2 = 0.f;
#pragma unroll 4
    for (int m = 0; m < M_DIM; m++) {
        float v = xp[m];
        s += v;
        s2 += v * v;
    }
    float mu = s * (1.0f / M_DIM);
    g_mu[b * C_DIM + c] = mu;
    float contrib = s2 * (1.0f / M_DIM) - mu * mu;

    __shared__ float red[C_DIM];
    red[c] = contrib;
    __syncthreads();
    for (int off = C_DIM / 2; off > 0; off >>= 1) {
        if (c < off) red[c] += red[c + off];
        __syncthreads();
    }
    if (c == 0) g_norm[b] = red[0];
}

// ---------------------------------------------------------------------------
// Shared GEMM machinery: 128x128 tile, 8 warps (2x4), warp tile 64x32,
// double-buffered BK=16 stages, 3xFP16-split mma.sync.
// MODE: 0 plain store (+mirror), 1: 1.5I-0.5*acc (+mirror),
//       2: triu(acc*sqrt(norm)) -> packed out, 3: covariance epilogue
// ---------------------------------------------------------------------------
template <int MODE>
__device__ __forceinline__ void gemm_core(const float* __restrict__ Abase,  // A rows (ti0 pre-offset)
                                          const float* __restrict__ Bbase,  // B rows (tj0 pre-offset)
                                          int strideAB, int NC,
                                          float* __restrict__ Cout,
                                          int b, int ti0, int tj0, bool mirror) {
    __shared__ __align__(16) char smem[2][4][TILEB];  // [stage][Ah,Al,Bh,Bl]

    int tid = threadIdx.x, lane = tid & 31, wid = tid >> 5;
    int wr = wid >> 2, wc = wid & 3;

    float acc[4][4][4] = {};
    float4 ra[2], rb[2];

    // prologue: load stage 0
    {
        int k0 = 0;
#pragma unroll
        for (int p = 0; p < 2; p++) {
            int idx = tid + p * 256;
            int r = idx >> 2, cg = idx & 3;
            int kcol = k0 + cg * 4;
            float4 va = make_float4(0.f, 0.f, 0.f, 0.f);
            float4 vb = make_float4(0.f, 0.f, 0.f, 0.f);
            if (MODE != 3 || kcol < M_DIM) {
                va = *(const float4*)&Abase[(size_t)r * strideAB + kcol];
                vb = *(const float4*)&Bbase[(size_t)r * strideAB + kcol];
            }
            split_sts(&smem[0][0][r * ROWB + cg * 8], &smem[0][1][r * ROWB + cg * 8], va);
            split_sts(&smem[0][2][r * ROWB + cg * 8], &smem[0][3][r * ROWB + cg * 8], vb);
        }
    }
    __syncthreads();

    for (int kc = 0; kc < NC; kc++) {
        int s = kc & 1;
        // prefetch next stage into registers
        if (kc + 1 < NC) {
            int k0 = (kc + 1) * BK;
#pragma unroll
            for (int p = 0; p < 2; p++) {
                int idx = tid + p * 256;
                int r = idx >> 2, cg = idx & 3;
                int kcol = k0 + cg * 4;
                ra[p] = make_float4(0.f, 0.f, 0.f, 0.f);
                rb[p] = make_float4(0.f, 0.f, 0.f, 0.f);
                if (MODE != 3 || kcol < M_DIM) {
                    ra[p] = *(const float4*)&Abase[(size_t)r * strideAB + kcol];
                    rb[p] = *(const float4*)&Bbase[(size_t)r * strideAB + kcol];
                }
            }
        }

        // compute on stage s
        {
            uint32_t abase_h = (uint32_t)__cvta_generic_to_shared(&smem[s][0][0]);
            uint32_t abase_l = (uint32_t)__cvta_generic_to_shared(&smem[s][1][0]);
            uint32_t bbase_h = (uint32_t)__cvta_generic_to_shared(&smem[s][2][0]);
            uint32_t bbase_l = (uint32_t)__cvta_generic_to_shared(&smem[s][3][0]);

            uint32_t Bh[8], Bl[8];
#pragma unroll
            for (int bj = 0; bj < 2; bj++) {
                ldmx4(&Bh[4 * bj], frag_addr(bbase_h, wc * 32 + bj * 16, lane));
                ldmx4(&Bl[4 * bj], frag_addr(bbase_l, wc * 32 + bj * 16, lane));
            }
#pragma unroll
            for (int fi = 0; fi < 4; fi++) {
                uint32_t Ah4[4], Al4[4];
                ldmx4(Ah4, frag_addr(abase_h, wr * 64 + fi * 16, lane));
                ldmx4(Al4, frag_addr(abase_l, wr * 64 + fi * 16, lane));
#pragma unroll
                for (int fj = 0; fj < 4; fj++) {
                    int bj = fj >> 1, o = fj & 1;
                    uint32_t b0h = Bh[4 * bj + o],     b1h = Bh[4 * bj + 2 + o];
                    uint32_t b0l = Bl[4 * bj + o],     b1l = Bl[4 * bj + 2 + o];
                    mma16816(acc[fi][fj], Ah4, b0h, b1h);  // hi*hi
                    mma16816(acc[fi][fj], Ah4, b0l, b1l);  // hi*lo
                    mma16816(acc[fi][fj], Al4, b0h, b1h);  // lo*hi
                }
            }
        }

        // store prefetched data into the other buffer
        if (kc + 1 < NC) {
            int ns = (kc + 1) & 1;
#pragma unroll
            for (int p = 0; p < 2; p++) {
                int idx = tid + p * 256;
                int r = idx >> 2, cg = idx & 3;
                split_sts(&smem[ns][0][r * ROWB + cg * 8], &smem[ns][1][r * ROWB + cg * 8], ra[p]);
                split_sts(&smem[ns][2][r * ROWB + cg * 8], &smem[ns][3][r * ROWB + cg * 8], rb[p]);
            }
        }
        __syncthreads();
    }

    // ------------------------- epilogue -------------------------
    int g = lane >> 2, t = lane & 3;

    if (MODE == 2) {
        float sc = sqrtf(g_norm[b]);
        float* outb = Cout + (size_t)b * TRIU_LEN;
#pragma unroll
        for (int fi = 0; fi < 4; fi++) {
#pragma unroll
            for (int fj = 0; fj < 4; fj++) {
                int gi0 = ti0 + wr * 64 + fi * 16 + g;
                int gj0 = tj0 + wc * 32 + fj * 8 + 2 * t;
#pragma unroll
                for (int h = 0; h < 2; h++) {
                    int gi = gi0 + h * 8;
                    int rowbase = gi * C_DIM - (gi * (gi - 1)) / 2 - gi;
                    float v0 = acc[fi][fj][2 * h]     * sc;
                    float v1 = acc[fi][fj][2 * h + 1] * sc;
                    if (gj0 >= gi)     outb[rowbase + gj0]     = v0;
                    if (gj0 + 1 >= gi) outb[rowbase + gj0 + 1] = v1;
                }
            }
        }
    } else if (MODE == 3) {
        float rn = 1.0f / g_norm[b];
        const float* mub = g_mu + b * C_DIM;
        float* Ab = g_A + (size_t)b * MAT_ELEMS;
        float* Zb = g_Z + (size_t)b * MAT_ELEMS;
#pragma unroll
        for (int fi = 0; fi < 4; fi++) {
#pragma unroll
            for (int fj = 0; fj < 4; fj++) {
                int gi0 = ti0 + wr * 64 + fi * 16 + g;
                int gj0 = tj0 + wc * 32 + fj * 8 + 2 * t;
                float mj0 = mub[gj0], mj1 = mub[gj0 + 1];
#pragma unroll
                for (int h = 0; h < 2; h++) {
                    int gi = gi0 + h * 8;
                    float mi = mub[gi];
                    float v0 = (acc[fi][fj][2 * h]     * (1.0f / M_DIM) - mi * mj0) * rn;
                    float v1 = (acc[fi][fj][2 * h + 1] * (1.0f / M_DIM) - mi * mj1) * rn;
                    float z0 = (gi == gj0     ? 1.5f : 0.0f) - 0.5f * v0;
                    float z1 = (gi == gj0 + 1 ? 1.5f : 0.0f) - 0.5f * v1;
                    *(float2*)&Ab[gi * C_DIM + gj0] = make_float2(v0, v1);
                    *(float2*)&Zb[gi * C_DIM + gj0] = make_float2(z0, z1);
                    if (mirror) {
                        Ab[gj0 * C_DIM + gi] = v0;       Ab[(gj0 + 1) * C_DIM + gi] = v1;
                        Zb[gj0 * C_DIM + gi] = z0;       Zb[(gj0 + 1) * C_DIM + gi] = z1;
                    }
                }
            }
        }
    } else {
        float* Cb = Cout + (size_t)b * MAT_ELEMS;
#pragma unroll
        for (int fi = 0; fi < 4; fi++) {
#pragma unroll
            for (int fj = 0; fj < 4; fj++) {
                int gi0 = ti0 + wr * 64 + fi * 16 + g;
                int gj0 = tj0 + wc * 32 + fj * 8 + 2 * t;
#pragma unroll
                for (int h = 0; h < 2; h++) {
                    int gi = gi0 + h * 8;
                    float r0 = acc[fi][fj][2 * h], r1 = acc[fi][fj][2 * h + 1];
                    float v0 = (MODE == 1) ? ((gi == gj0     ? 1.5f : 0.0f) - 0.5f * r0) : r0;
                    float v1 = (MODE == 1) ? ((gi == gj0 + 1 ? 1.5f : 0.0f) - 0.5f * r1) : r1;
                    *(float2*)&Cb[gi * C_DIM + gj0] = make_float2(v0, v1);
                    if (mirror) {
                        Cb[gj0 * C_DIM + gi] = v0;
                        Cb[(gj0 + 1) * C_DIM + gi] = v1;
                    }
                }
            }
        }
    }
}

// ---------------------------------------------------------------------------
// Kernels (symmetric 3-tile grid: bx 0=(0,0), 1=(0,1) mirrored, 2=(1,1))
// ---------------------------------------------------------------------------
__global__ __launch_bounds__(256) void cov_kernel(const float* __restrict__ x) {
    int bx = blockIdx.x, b = blockIdx.z;
    int ti0 = (bx == 2) ? 128 : 0;
    int tj0 = (bx >= 1) ? 128 : 0;
    const float* xb = x + (size_t)b * C_DIM * M_DIM;
    gemm_core<3>(xb + (size_t)ti0 * M_DIM, xb + (size_t)tj0 * M_DIM,
                 M_DIM, 13 /* ceil(196/16) */, nullptr, b, ti0, tj0, bx == 1);
}

template <int MODE>
__global__ __launch_bounds__(256) void ns_gemm(const float* __restrict__ A,
                                               const float* __restrict__ B,
                                               float* __restrict__ C) {
    int bx = blockIdx.x, b = blockIdx.z;
    int ti0 = (bx == 2) ? 128 : 0;
    int tj0 = (bx >= 1) ? 128 : 0;
    gemm_core<MODE>(A + (size_t)b * MAT_ELEMS + (size_t)ti0 * C_DIM,
                    B + (size_t)b * MAT_ELEMS + (size_t)tj0 * C_DIM,
                    C_DIM, 16, C, b, ti0, tj0, bx == 1);
}

__global__ __launch_bounds__(256) void ns_gemm_dual(
    const float* __restrict__ A1, const float* __restrict__ B1, float* __restrict__ C1,
    const float* __restrict__ A2, const float* __restrict__ B2, float* __restrict__ C2) {
    int bx = blockIdx.x, b = blockIdx.z;
    int ti0 = (bx == 2) ? 128 : 0;
    int tj0 = (bx >= 1) ? 128 : 0;
    const float* A = (blockIdx.y == 0) ? A1 : A2;
    const float* B = (blockIdx.y == 0) ? B1 : B2;
    float* C = (blockIdx.y == 0) ? C1 : C2;
    gemm_core<0>(A + (size_t)b * MAT_ELEMS + (size_t)ti0 * C_DIM,
                 B + (size_t)b * MAT_ELEMS + (size_t)tj0 * C_DIM,
                 C_DIM, 16, C, b, ti0, tj0, bx == 1);
}

// ---------------------------------------------------------------------------
// Launch: Newton-Schulz (ITER_N = 3)
//   ZY0 = 1.5I - 0.5 Ahat; Y1 = Ahat@ZY0; Z1 = ZY0
//   ZY1 = 1.5I - 0.5 Z1@Y1; Y2 = Y1@ZY1; Z2 = ZY1@Z1
//   E   = 1.5I - 0.5 Z2@Y2; out = triu((Y2@E)*sqrt(normA))
// ---------------------------------------------------------------------------
extern "C" void kernel_launch(void* const* d_in, const int* in_sizes, int n_in,
                              void* d_out, int out_size) {
    const float* x = (const float*)d_in[0];
    float* out = (float*)d_out;

    float *A, *Y, *Z, *ZY, *T;
    cudaGetSymbolAddress((void**)&A,  g_A);
    cudaGetSymbolAddress((void**)&Y,  g_Y);
    cudaGetSymbolAddress((void**)&Z,  g_Z);
    cudaGetSymbolAddress((void**)&ZY, g_ZY);
    cudaGetSymbolAddress((void**)&T,  g_T);

    dim3 grid(3, 1, BATCH), grid2(3, 2, BATCH);

    stats_kernel<<<BATCH, C_DIM>>>(x);
    cov_kernel<<<grid, 256>>>(x);                  // g_A = Ahat, g_Z = ZY0 (= Z1)
    ns_gemm<0><<<grid, 256>>>(A, Z, Y);            // Y1 = Ahat @ ZY0
    ns_gemm<1><<<grid, 256>>>(Z, Y, ZY);           // ZY1 = 1.5I - 0.5 Z1@Y1
    ns_gemm_dual<<<grid2, 256>>>(Y, ZY, A,         // Y2 = Y1 @ ZY1
                                 ZY, Z, T);        // Z2 = ZY1 @ Z1
    ns_gemm<1><<<grid, 256>>>(T, A, ZY);           // E = 1.5I - 0.5 Z2@Y2
    ns_gemm<2><<<grid, 256>>>(A, ZY, out);         // out = triu((Y2@E)*sqrt(normA))
}